// round 2
// baseline (speedup 1.0000x reference)
#include <cuda_runtime.h>

#define BSZ 8192
#define TSTEPS 128
#define NN 25
// HID = 4, gates = 16

// Scratch (allocation-free rule: static __device__ arrays)
__device__ float g_xT[TSTEPS * NN * BSZ];       // [t][i][b]  ~105 MB
__device__ float g_H[BSZ * 200];                // final hidden concat, (bs, 200)

typedef unsigned long long u64;

// ---------------------------------------------------------------------------
// f32x2 packed helpers (Blackwell FFMA2 only reachable via PTX)
// ---------------------------------------------------------------------------
__device__ __forceinline__ u64 packf2(float lo, float hi) {
    u64 r; asm("mov.b64 %0, {%1, %2};" : "=l"(r) : "f"(lo), "f"(hi)); return r;
}
__device__ __forceinline__ u64 bcast2(float v) { return packf2(v, v); }
__device__ __forceinline__ void unpackf2(u64 v, float& lo, float& hi) {
    asm("mov.b64 {%0, %1}, %2;" : "=f"(lo), "=f"(hi) : "l"(v));
}
__device__ __forceinline__ u64 fma2(u64 a, u64 b, u64 c) {
    u64 r; asm("fma.rn.f32x2 %0, %1, %2, %3;" : "=l"(r) : "l"(a), "l"(b), "l"(c));
    return r;
}

// ---------------------------------------------------------------------------
// MUFU.TANH-based activations (1 MUFU each)
// ---------------------------------------------------------------------------
__device__ __forceinline__ float tanh_mufu(float x) {
    float y; asm("tanh.approx.f32 %0, %1;" : "=f"(y) : "f"(x)); return y;
}
__device__ __forceinline__ float sig_mufu(float x) {
    return fmaf(0.5f, tanh_mufu(0.5f * x), 0.5f);
}
__device__ __forceinline__ float sigf(float x) {   // precise (FF head)
    return __fdividef(1.0f, 1.0f + __expf(-x));
}

// ---------------------------------------------------------------------------
// Kernel 1: transpose x (bs, N, T) -> xT[t][i][b]
// ---------------------------------------------------------------------------
__global__ void transpose_kernel(const float* __restrict__ x) {
    __shared__ float tile[32][33];
    int i  = blockIdx.z;
    int b0 = blockIdx.x * 32;
    int t0 = blockIdx.y * 32;
    int tx = threadIdx.x, ty = threadIdx.y;
#pragma unroll
    for (int r = 0; r < 4; r++) {
        int b = b0 + ty + r * 8;
        int t = t0 + tx;
        tile[ty + r * 8][tx] = x[(b * NN + i) * TSTEPS + t];
    }
    __syncthreads();
#pragma unroll
    for (int r = 0; r < 4; r++) {
        int t = t0 + ty + r * 8;
        int b = b0 + tx;
        g_xT[(t * NN + i) * BSZ + b] = tile[tx][ty + r * 8];
    }
}

// ---------------------------------------------------------------------------
// Kernel 2: grid-LSTM recurrence.
// 4 threads per (batch, direction) group; thread u owns hidden unit u and
// computes gate columns {u, 4+u, 8+u, 12+u} as 2 packed f32x2 accumulators.
// h gather across units via 3-shuffle butterfly; neighbor h[.][3] broadcast
// from lane 3 of the group.
// ---------------------------------------------------------------------------
__global__ __launch_bounds__(128) void rec_kernel(
    const float* __restrict__ h0f, const float* __restrict__ c0f,
    const float* __restrict__ h0b, const float* __restrict__ c0b,
    const float* __restrict__ Wxf, const float* __restrict__ Whf,
    const float* __restrict__ Wnf, const float* __restrict__ bf,
    const float* __restrict__ Wxb, const float* __restrict__ Whb,
    const float* __restrict__ Wnb, const float* __restrict__ bbk) {
    int tid = blockIdx.x * 128 + threadIdx.x;  // 0 .. 65535
    int u   = tid & 3;
    int gid = tid >> 2;                        // group = (dir, b)
    int b   = gid & (BSZ - 1);
    int dir = gid >> 13;                       // 0 = fwd, 1 = bwd

    const float* Wx = dir ? Wxb : Wxf;
    const float* Wh = dir ? Whb : Whf;
    const float* Wn = dir ? Wnb : Wnf;
    const float* bv = dir ? bbk : bf;
    const float* h0 = dir ? h0b : h0f;
    const float* c0 = dir ? c0b : c0f;

    // Gate columns for this thread: pair 0 = (ig, fg), pair 1 = (og, cc)
    int c0i = u, c1i = 4 + u, c2i = 8 + u, c3i = 12 + u;

    u64 wxp[2], bp[2], whp[4][2], wup[2], wdp[2], wlp[2], wrp[2];
    wxp[0] = packf2(Wx[c0i], Wx[c1i]);  wxp[1] = packf2(Wx[c2i], Wx[c3i]);
    bp[0]  = packf2(bv[c0i], bv[c1i]);  bp[1]  = packf2(bv[c2i], bv[c3i]);
#pragma unroll
    for (int j = 0; j < 4; j++) {
        int uj = u ^ j;   // butterfly arrival order: a_j holds h of unit u^j
        whp[j][0] = packf2(Wh[uj * 16 + c0i], Wh[uj * 16 + c1i]);
        whp[j][1] = packf2(Wh[uj * 16 + c2i], Wh[uj * 16 + c3i]);
    }
    wup[0] = packf2(Wn[0 * 16 + c0i], Wn[0 * 16 + c1i]);
    wup[1] = packf2(Wn[0 * 16 + c2i], Wn[0 * 16 + c3i]);
    wdp[0] = packf2(Wn[1 * 16 + c0i], Wn[1 * 16 + c1i]);
    wdp[1] = packf2(Wn[1 * 16 + c2i], Wn[1 * 16 + c3i]);
    {
        // fwd neighbor order [up,dn,lf,rt]; bwd order [up,dn,rt,lf]
        int rl = dir ? 3 : 2;   // row index in Wn providing the LEFT weight
        int rr = dir ? 2 : 3;
        wlp[0] = packf2(Wn[rl * 16 + c0i], Wn[rl * 16 + c1i]);
        wlp[1] = packf2(Wn[rl * 16 + c2i], Wn[rl * 16 + c3i]);
        wrp[0] = packf2(Wn[rr * 16 + c0i], Wn[rr * 16 + c1i]);
        wrp[1] = packf2(Wn[rr * 16 + c2i], Wn[rr * 16 + c3i]);
    }

    float h[NN], c[NN];
#pragma unroll
    for (int i = 0; i < NN; i++) {
        h[i] = h0[(i * BSZ + b) * 4 + u];
        c[i] = c0[(i * BSZ + b) * 4 + u];
    }

#pragma unroll 1
    for (int t = 0; t < TSTEPS; t++) {
        int tt = dir ? (TSTEPS - 1 - t) : t;
        const float* xrow = g_xT + (tt * NN) * BSZ + b;
#pragma unroll
        for (int i = 0; i < NN; i++) {
            float xv = xrow[i * BSZ];
            float a0 = h[i];
            float a1 = __shfl_xor_sync(0xffffffffu, a0, 1, 4);
            float a2 = __shfl_xor_sync(0xffffffffu, a0, 2, 4);
            float a3 = __shfl_xor_sync(0xffffffffu, a1, 2, 4);

            u64 vx = bcast2(xv);
            u64 gA = fma2(vx, wxp[0], bp[0]);
            u64 gB = fma2(vx, wxp[1], bp[1]);
            u64 v0 = bcast2(a0), v1 = bcast2(a1), v2 = bcast2(a2), v3 = bcast2(a3);
            gA = fma2(v0, whp[0][0], gA); gB = fma2(v0, whp[0][1], gB);
            gA = fma2(v1, whp[1][0], gA); gB = fma2(v1, whp[1][1], gB);
            gA = fma2(v2, whp[2][0], gA); gB = fma2(v2, whp[2][1], gB);
            gA = fma2(v3, whp[3][0], gA); gB = fma2(v3, whp[3][1], gB);

            if (i >= 5) {   // up neighbor (updated this step)
                u64 nv = bcast2(__shfl_sync(0xffffffffu, h[i - 5], 3, 4));
                gA = fma2(nv, wup[0], gA); gB = fma2(nv, wup[1], gB);
            }
            if (i < 20) {   // down neighbor (previous step)
                u64 nv = bcast2(__shfl_sync(0xffffffffu, h[i + 5], 3, 4));
                gA = fma2(nv, wdp[0], gA); gB = fma2(nv, wdp[1], gB);
            }
            if (i >= 1) {   // left neighbor (updated this step, row-wrap)
                u64 nv = bcast2(__shfl_sync(0xffffffffu, h[i - 1], 3, 4));
                gA = fma2(nv, wlp[0], gA); gB = fma2(nv, wlp[1], gB);
            }
            if (i < 24) {   // right neighbor (previous step, row-wrap)
                u64 nv = bcast2(__shfl_sync(0xffffffffu, h[i + 1], 3, 4));
                gA = fma2(nv, wrp[0], gA); gB = fma2(nv, wrp[1], gB);
            }

            float g0, g1, g2, g3;
            unpackf2(gA, g0, g1);
            unpackf2(gB, g2, g3);

            float si = sig_mufu(g0);
            float sf = sig_mufu(g1);
            float so = sig_mufu(g2);
            float tc = tanh_mufu(g3);
            float nc = fmaf(sf, c[i], si * tc);
            c[i] = nc;
            h[i] = so * tanh_mufu(nc);
        }
    }

    // H[b, i*8 + dir*4 + u] = h[i]
#pragma unroll
    for (int i = 0; i < NN; i++) {
        g_H[b * 200 + i * 8 + dir * 4 + u] = h[i];
    }
}

// ---------------------------------------------------------------------------
// Kernel 3: FF head. 16 batch rows per block, 128 threads (one per neuron).
// ff = sigmoid(H @ W_ff + b_ff); out = softmax(ff @ W_out + b_out)
// ---------------------------------------------------------------------------
__global__ void ff_kernel(const float* __restrict__ Wff, const float* __restrict__ bff,
                          const float* __restrict__ Wout, const float* __restrict__ bout,
                          float* __restrict__ out) {
    __shared__ float Hs[16 * 200];
    __shared__ float Fs[16 * 128];
    int k  = threadIdx.x;        // neuron 0..127
    int b0 = blockIdx.x * 16;

    for (int idx = k; idx < 16 * 200; idx += 128)
        Hs[idx] = g_H[b0 * 200 + idx];
    __syncthreads();

    float acc[16];
    float bk = bff[k];
#pragma unroll
    for (int m = 0; m < 16; m++) acc[m] = bk;
#pragma unroll 4
    for (int j = 0; j < 200; j++) {
        float w = Wff[j * 128 + k];
#pragma unroll
        for (int m = 0; m < 16; m++) acc[m] = fmaf(Hs[m * 200 + j], w, acc[m]);
    }
#pragma unroll
    for (int m = 0; m < 16; m++) Fs[m * 128 + k] = sigf(acc[m]);
    __syncthreads();

    if (k < 16) {
        float s0 = bout[0], s1 = bout[1];
#pragma unroll 4
        for (int j = 0; j < 128; j++) {
            float f = Fs[k * 128 + j];
            s0 = fmaf(f, Wout[j * 2 + 0], s0);
            s1 = fmaf(f, Wout[j * 2 + 1], s1);
        }
        // softmax over 2 logits == sigmoid of difference
        out[(b0 + k) * 2 + 0] = sigf(s0 - s1);
        out[(b0 + k) * 2 + 1] = sigf(s1 - s0);
    }
}

// ---------------------------------------------------------------------------
extern "C" void kernel_launch(void* const* d_in, const int* in_sizes, int n_in,
                              void* d_out, int out_size) {
    const float* x    = (const float*)d_in[0];
    const float* h0f  = (const float*)d_in[1];
    const float* c0f  = (const float*)d_in[2];
    const float* h0b  = (const float*)d_in[3];
    const float* c0b  = (const float*)d_in[4];
    const float* Wxf  = (const float*)d_in[5];
    const float* Whf  = (const float*)d_in[6];
    const float* Wnf  = (const float*)d_in[7];
    const float* bf   = (const float*)d_in[8];
    const float* Wxb  = (const float*)d_in[9];
    const float* Whb  = (const float*)d_in[10];
    const float* Wnb  = (const float*)d_in[11];
    const float* bb   = (const float*)d_in[12];
    const float* Wff  = (const float*)d_in[13];
    const float* bff  = (const float*)d_in[14];
    const float* Wout = (const float*)d_in[15];
    const float* bout = (const float*)d_in[16];

    transpose_kernel<<<dim3(BSZ / 32, TSTEPS / 32, NN), dim3(32, 8)>>>(x);
    rec_kernel<<<65536 / 128, 128>>>(h0f, c0f, h0b, c0b,
                                     Wxf, Whf, Wnf, bf,
                                     Wxb, Whb, Wnb, bb);
    ff_kernel<<<BSZ / 16, 128>>>(Wff, bff, Wout, bout, (float*)d_out);
}

// round 3
// speedup vs baseline: 1.3308x; 1.3308x over previous
#include <cuda_runtime.h>

#define BSZ 8192
#define TSTEPS 128
#define NN 25
// HID = 4, gates = 16

// Scratch (allocation-free rule: static __device__ arrays)
__device__ float g_xT[TSTEPS * NN * BSZ];       // [t][i][b]  ~105 MB
__device__ float g_H[BSZ * 200];                // final hidden concat, (bs, 200)

typedef unsigned long long u64;

// ---------------------------------------------------------------------------
// f32x2 packed helpers
// ---------------------------------------------------------------------------
__device__ __forceinline__ u64 packf2(float lo, float hi) {
    u64 r; asm("mov.b64 %0, {%1, %2};" : "=l"(r) : "f"(lo), "f"(hi)); return r;
}
__device__ __forceinline__ u64 bcast2(float v) { return packf2(v, v); }
__device__ __forceinline__ void unpackf2(u64 v, float& lo, float& hi) {
    asm("mov.b64 {%0, %1}, %2;" : "=f"(lo), "=f"(hi) : "l"(v));
}
__device__ __forceinline__ u64 fma2(u64 a, u64 b, u64 c) {
    u64 r; asm("fma.rn.f32x2 %0, %1, %2, %3;" : "=l"(r) : "l"(a), "l"(b), "l"(c));
    return r;
}
// 64-bit shuffles within the 4-lane group (2x SHFL.32)
__device__ __forceinline__ u64 shflx64(u64 v, int m) {
    unsigned lo = (unsigned)v, hi = (unsigned)(v >> 32);
    lo = __shfl_xor_sync(0xffffffffu, lo, m, 4);
    hi = __shfl_xor_sync(0xffffffffu, hi, m, 4);
    return ((u64)hi << 32) | lo;
}
__device__ __forceinline__ u64 shflb64(u64 v) {   // broadcast from lane 3 of group
    unsigned lo = (unsigned)v, hi = (unsigned)(v >> 32);
    lo = __shfl_sync(0xffffffffu, lo, 3, 4);
    hi = __shfl_sync(0xffffffffu, hi, 3, 4);
    return ((u64)hi << 32) | lo;
}

// ---------------------------------------------------------------------------
// MUFU.TANH-based activations (1 MUFU each)
// ---------------------------------------------------------------------------
__device__ __forceinline__ float tanh_mufu(float x) {
    float y; asm("tanh.approx.f32 %0, %1;" : "=f"(y) : "f"(x)); return y;
}
__device__ __forceinline__ float sigf(float x) {   // precise (FF head)
    return __fdividef(1.0f, 1.0f + __expf(-x));
}

// ---------------------------------------------------------------------------
// Kernel 1: transpose x (bs, N, T) -> xT[t][i][b]
// ---------------------------------------------------------------------------
__global__ void transpose_kernel(const float* __restrict__ x) {
    __shared__ float tile[32][33];
    int i  = blockIdx.z;
    int b0 = blockIdx.x * 32;
    int t0 = blockIdx.y * 32;
    int tx = threadIdx.x, ty = threadIdx.y;
#pragma unroll
    for (int r = 0; r < 4; r++) {
        int b = b0 + ty + r * 8;
        int t = t0 + tx;
        tile[ty + r * 8][tx] = x[(b * NN + i) * TSTEPS + t];
    }
    __syncthreads();
#pragma unroll
    for (int r = 0; r < 4; r++) {
        int t = t0 + ty + r * 8;
        int b = b0 + tx;
        g_xT[(t * NN + i) * BSZ + b] = tile[tx][ty + r * 8];
    }
}

// ---------------------------------------------------------------------------
// Kernel 2: grid-LSTM recurrence, batch-pair packed in f32x2.
// 4 threads per group; group = (dir, batch-pair). Thread u owns hidden unit u
// for TWO batch elements (b0 = 2*pair, b1 = b0+1), packed (lo,hi) in u64.
// Gate columns {u,4+u,8+u,12+u} kept as 4 packed accumulators G[g].
// Weights pre-broadcast to u64 once; sigmoid's 0.5 factor folded into the
// ig/fg/og weight columns.
// ---------------------------------------------------------------------------
__global__ __launch_bounds__(64) void rec_kernel(
    const float* __restrict__ h0f, const float* __restrict__ c0f,
    const float* __restrict__ h0b, const float* __restrict__ c0b,
    const float* __restrict__ Wxf, const float* __restrict__ Whf,
    const float* __restrict__ Wnf, const float* __restrict__ bf,
    const float* __restrict__ Wxb, const float* __restrict__ Whb,
    const float* __restrict__ Wnb, const float* __restrict__ bbk) {
    int tid  = blockIdx.x * 64 + threadIdx.x;  // 0 .. 32767
    int u    = tid & 3;
    int gid  = tid >> 2;                       // 0 .. 8191
    int pair = gid & 4095;
    int dir  = gid >> 12;                      // 0 = fwd, 1 = bwd
    int b0   = pair * 2;

    const float* Wx = dir ? Wxb : Wxf;
    const float* Wh = dir ? Whb : Whf;
    const float* Wn = dir ? Wnb : Wnf;
    const float* bv = dir ? bbk : bf;
    const float* h0 = dir ? h0b : h0f;
    const float* c0 = dir ? c0b : c0f;

    // Per-gate scale: 0.5 for sigmoid gates (g=0,1,2), 1.0 for cc (g=3)
    u64 wx2[4], b2[4], wh2[4][4], wu2[4], wd2[4], wl2[4], wr2[4];
    int rl = dir ? 3 : 2;   // Wn row providing LEFT weight
    int rr = dir ? 2 : 3;
#pragma unroll
    for (int g = 0; g < 4; g++) {
        float s   = (g == 3) ? 1.0f : 0.5f;
        int   col = g * 4 + u;
        wx2[g] = bcast2(s * Wx[col]);
        b2[g]  = bcast2(s * bv[col]);
#pragma unroll
        for (int j = 0; j < 4; j++)
            wh2[j][g] = bcast2(s * Wh[(u ^ j) * 16 + col]);  // j-th butterfly arrival
        wu2[g] = bcast2(s * Wn[0 * 16 + col]);
        wd2[g] = bcast2(s * Wn[1 * 16 + col]);
        wl2[g] = bcast2(s * Wn[rl * 16 + col]);
        wr2[g] = bcast2(s * Wn[rr * 16 + col]);
    }

    u64 h[NN];
    float ca[NN], cb[NN];
#pragma unroll
    for (int i = 0; i < NN; i++) {
        int base = (i * BSZ + b0) * 4 + u;
        h[i]  = packf2(h0[base], h0[base + 4]);
        ca[i] = c0[base];
        cb[i] = c0[base + 4];
    }

#pragma unroll 1
    for (int t = 0; t < TSTEPS; t++) {
        int tt = dir ? (TSTEPS - 1 - t) : t;
        const double* xrow = (const double*)(g_xT + (tt * NN) * BSZ + b0);
#pragma unroll
        for (int i = 0; i < NN; i++) {
            u64 vx = ((const u64*)xrow)[i * (BSZ / 2)];
            u64 v0 = h[i];
            u64 v1 = shflx64(v0, 1);
            u64 v2 = shflx64(v0, 2);
            u64 v3 = shflx64(v0, 3);

            u64 G[4];
#pragma unroll
            for (int g = 0; g < 4; g++) {
                G[g] = fma2(vx, wx2[g], b2[g]);
                G[g] = fma2(v0, wh2[0][g], G[g]);
                G[g] = fma2(v1, wh2[1][g], G[g]);
                G[g] = fma2(v2, wh2[2][g], G[g]);
                G[g] = fma2(v3, wh2[3][g], G[g]);
            }
            if (i >= 5) {   // up neighbor (updated this step)
                u64 nv = shflb64(h[i - 5]);
#pragma unroll
                for (int g = 0; g < 4; g++) G[g] = fma2(nv, wu2[g], G[g]);
            }
            if (i < 20) {   // down neighbor (previous step)
                u64 nv = shflb64(h[i + 5]);
#pragma unroll
                for (int g = 0; g < 4; g++) G[g] = fma2(nv, wd2[g], G[g]);
            }
            if (i >= 1) {   // left neighbor (updated this step, row-wrap)
                u64 nv = shflb64(h[i - 1]);
#pragma unroll
                for (int g = 0; g < 4; g++) G[g] = fma2(nv, wl2[g], G[g]);
            }
            if (i < 24) {   // right neighbor (previous step, row-wrap)
                u64 nv = shflb64(h[i + 1]);
#pragma unroll
                for (int g = 0; g < 4; g++) G[g] = fma2(nv, wr2[g], G[g]);
            }

            float i_a, i_b, f_a, f_b, o_a, o_b, c_a, c_b;
            unpackf2(G[0], i_a, i_b);
            unpackf2(G[1], f_a, f_b);
            unpackf2(G[2], o_a, o_b);
            unpackf2(G[3], c_a, c_b);

            // batch 0 (gates pre-scaled by 0.5 for sigmoids)
            float sia = fmaf(0.5f, tanh_mufu(i_a), 0.5f);
            float sfa = fmaf(0.5f, tanh_mufu(f_a), 0.5f);
            float soa = fmaf(0.5f, tanh_mufu(o_a), 0.5f);
            float tca = tanh_mufu(c_a);
            float nca = fmaf(sfa, ca[i], sia * tca);
            ca[i] = nca;
            float nha = soa * tanh_mufu(nca);
            // batch 1
            float sib = fmaf(0.5f, tanh_mufu(i_b), 0.5f);
            float sfb = fmaf(0.5f, tanh_mufu(f_b), 0.5f);
            float sob = fmaf(0.5f, tanh_mufu(o_b), 0.5f);
            float tcb = tanh_mufu(c_b);
            float ncb = fmaf(sfb, cb[i], sib * tcb);
            cb[i] = ncb;
            float nhb = sob * tanh_mufu(ncb);

            h[i] = packf2(nha, nhb);
        }
    }

    // H[b, i*8 + dir*4 + u] = h[i]
#pragma unroll
    for (int i = 0; i < NN; i++) {
        float ha, hb;
        unpackf2(h[i], ha, hb);
        g_H[b0 * 200 + i * 8 + dir * 4 + u]       = ha;
        g_H[(b0 + 1) * 200 + i * 8 + dir * 4 + u] = hb;
    }
}

// ---------------------------------------------------------------------------
// Kernel 3: FF head. 16 batch rows per block, 128 threads (one per neuron).
// ff = sigmoid(H @ W_ff + b_ff); out = softmax(ff @ W_out + b_out)
// ---------------------------------------------------------------------------
__global__ void ff_kernel(const float* __restrict__ Wff, const float* __restrict__ bff,
                          const float* __restrict__ Wout, const float* __restrict__ bout,
                          float* __restrict__ out) {
    __shared__ float Hs[16 * 200];
    __shared__ float Fs[16 * 128];
    int k  = threadIdx.x;        // neuron 0..127
    int b0 = blockIdx.x * 16;

    for (int idx = k; idx < 16 * 200; idx += 128)
        Hs[idx] = g_H[b0 * 200 + idx];
    __syncthreads();

    float acc[16];
    float bk = bff[k];
#pragma unroll
    for (int m = 0; m < 16; m++) acc[m] = bk;
#pragma unroll 4
    for (int j = 0; j < 200; j++) {
        float w = Wff[j * 128 + k];
#pragma unroll
        for (int m = 0; m < 16; m++) acc[m] = fmaf(Hs[m * 200 + j], w, acc[m]);
    }
#pragma unroll
    for (int m = 0; m < 16; m++) Fs[m * 128 + k] = sigf(acc[m]);
    __syncthreads();

    if (k < 16) {
        float s0 = bout[0], s1 = bout[1];
#pragma unroll 4
        for (int j = 0; j < 128; j++) {
            float f = Fs[k * 128 + j];
            s0 = fmaf(f, Wout[j * 2 + 0], s0);
            s1 = fmaf(f, Wout[j * 2 + 1], s1);
        }
        // softmax over 2 logits == sigmoid of difference
        out[(b0 + k) * 2 + 0] = sigf(s0 - s1);
        out[(b0 + k) * 2 + 1] = sigf(s1 - s0);
    }
}

// ---------------------------------------------------------------------------
extern "C" void kernel_launch(void* const* d_in, const int* in_sizes, int n_in,
                              void* d_out, int out_size) {
    const float* x    = (const float*)d_in[0];
    const float* h0f  = (const float*)d_in[1];
    const float* c0f  = (const float*)d_in[2];
    const float* h0b  = (const float*)d_in[3];
    const float* c0b  = (const float*)d_in[4];
    const float* Wxf  = (const float*)d_in[5];
    const float* Whf  = (const float*)d_in[6];
    const float* Wnf  = (const float*)d_in[7];
    const float* bf   = (const float*)d_in[8];
    const float* Wxb  = (const float*)d_in[9];
    const float* Whb  = (const float*)d_in[10];
    const float* Wnb  = (const float*)d_in[11];
    const float* bb   = (const float*)d_in[12];
    const float* Wff  = (const float*)d_in[13];
    const float* bff  = (const float*)d_in[14];
    const float* Wout = (const float*)d_in[15];
    const float* bout = (const float*)d_in[16];

    transpose_kernel<<<dim3(BSZ / 32, TSTEPS / 32, NN), dim3(32, 8)>>>(x);
    rec_kernel<<<32768 / 64, 64>>>(h0f, c0f, h0b, c0b,
                                   Wxf, Whf, Wnf, bf,
                                   Wxb, Whb, Wnb, bb);
    ff_kernel<<<BSZ / 16, 128>>>(Wff, bff, Wout, bout, (float*)d_out);
}